// round 4
// baseline (speedup 1.0000x reference)
#include <cuda_runtime.h>

#define SEQ 4096
#define HID 1024
#define NCTA 64
#define EPSF 1e-12f

// Scratch (allocation-free rule: __device__ globals)
__device__ float g_Xn[SEQ * HID];              // normalized embeddings
__device__ float g_P[SEQ * HID];               // W_hi @ x_t + b, precomputed
__device__ unsigned long long g_H[2 * HID];    // tagged h double buffer: hi32=tag, lo32=float bits

// ---------------- strong (relaxed-atomic) 8B ld/st ----------------
__device__ __forceinline__ unsigned long long ld_rlx(const unsigned long long* p) {
    unsigned long long v;
    asm volatile("ld.relaxed.gpu.global.u64 %0, [%1];" : "=l"(v) : "l"(p) : "memory");
    return v;
}
__device__ __forceinline__ void st_rlx(unsigned long long* p, unsigned long long v) {
    asm volatile("st.relaxed.gpu.global.u64 [%0], %1;" :: "l"(p), "l"(v) : "memory");
}

// ---------------- f32x2 packed helpers ----------------
__device__ __forceinline__ unsigned long long packff(float a, float b) {
    unsigned long long r;
    asm("mov.b64 %0, {%1,%2};" : "=l"(r) : "r"(__float_as_uint(a)), "r"(__float_as_uint(b)));
    return r;
}
__device__ __forceinline__ unsigned long long packlo(unsigned long long a, unsigned long long b) {
    unsigned long long r;
    asm("mov.b64 %0, {%1,%2};" : "=l"(r) : "r"((unsigned)a), "r"((unsigned)b));
    return r;
}
__device__ __forceinline__ void fma2(unsigned long long& acc, unsigned long long w, unsigned long long h) {
    asm("fma.rn.f32x2 %0, %1, %2, %0;" : "+l"(acc) : "l"(w), "l"(h));
}
__device__ __forceinline__ float sum2(unsigned long long a, unsigned long long b) {
    unsigned long long s;
    asm("add.rn.f32x2 %0, %1, %2;" : "=l"(s) : "l"(a), "l"(b));
    unsigned lo, hi;
    asm("mov.b64 {%0,%1}, %2;" : "=r"(lo), "=r"(hi) : "l"(s));
    return __uint_as_float(lo) + __uint_as_float(hi);
}

// ---------------- init: h0 -> out[0], tagged buf[0] (tag 1), clear buf[1] ----------------
__global__ __launch_bounds__(1024) void init_kernel(const float* __restrict__ h0,
                                                    float* __restrict__ out) {
    int i = threadIdx.x;
    float v = h0[i];
    out[i] = v;
    g_H[i]       = (1ull << 32) | (unsigned long long)__float_as_uint(v);
    g_H[HID + i] = 0ull;
}

// ---------------- embedding + L2 normalize ----------------
__global__ __launch_bounds__(256) void embed_kernel(const int* __restrict__ src,
                                                    const float* __restrict__ W) {
    const int t   = blockIdx.x;
    const int tid = threadIdx.x;
    const float4* row = reinterpret_cast<const float4*>(W) + (size_t)src[t] * (HID / 4);
    float4 v = row[tid];
    float s = v.x * v.x + v.y * v.y + v.z * v.z + v.w * v.w;
    #pragma unroll
    for (int o = 16; o; o >>= 1) s += __shfl_xor_sync(0xffffffffu, s, o);
    __shared__ float red[8];
    if ((tid & 31) == 0) red[tid >> 5] = s;
    __syncthreads();
    float tot = red[0] + red[1] + red[2] + red[3] + red[4] + red[5] + red[6] + red[7];
    float rn = 1.0f / fmaxf(sqrtf(tot), EPSF);
    float4 o4 = make_float4(v.x * rn, v.y * rn, v.z * rn, v.w * rn);
    reinterpret_cast<float4*>(g_Xn)[(size_t)t * (HID / 4) + tid] = o4;
}

// ---------------- GEMM: g_P[m][n] = sum_k g_Xn[m][k] * W_hi[n][k] + b[n] ----------------
#define BM 128
#define BN 64
#define BK 32
__global__ __launch_bounds__(256) void gemm_kernel(const float* __restrict__ Bw,
                                                   const float* __restrict__ bias) {
    __shared__ float As[BK][BM + 4];
    __shared__ float Bs[BK][BN + 4];
    const int tid = threadIdx.x;
    const int m0 = blockIdx.y * BM;
    const int n0 = blockIdx.x * BN;
    const int ty = tid >> 4;
    const int tx = tid & 15;

    float acc[8][4];
    #pragma unroll
    for (int i = 0; i < 8; i++)
        #pragma unroll
        for (int j = 0; j < 4; j++) acc[i][j] = 0.0f;

    for (int k0 = 0; k0 < HID; k0 += BK) {
        #pragma unroll
        for (int i = 0; i < 4; i++) {
            int idx = tid + i * 256;
            int r = idx >> 3;
            int kq = idx & 7;
            float4 f = reinterpret_cast<const float4*>(g_Xn)[(size_t)(m0 + r) * (HID / 4) + (k0 >> 2) + kq];
            As[kq * 4 + 0][r] = f.x;
            As[kq * 4 + 1][r] = f.y;
            As[kq * 4 + 2][r] = f.z;
            As[kq * 4 + 3][r] = f.w;
        }
        #pragma unroll
        for (int i = 0; i < 2; i++) {
            int idx = tid + i * 256;
            int r = idx >> 3;
            int kq = idx & 7;
            float4 f = reinterpret_cast<const float4*>(Bw)[(size_t)(n0 + r) * (HID / 4) + (k0 >> 2) + kq];
            Bs[kq * 4 + 0][r] = f.x;
            Bs[kq * 4 + 1][r] = f.y;
            Bs[kq * 4 + 2][r] = f.z;
            Bs[kq * 4 + 3][r] = f.w;
        }
        __syncthreads();
        #pragma unroll
        for (int k = 0; k < BK; k++) {
            float4 a0 = *reinterpret_cast<const float4*>(&As[k][ty * 8]);
            float4 a1 = *reinterpret_cast<const float4*>(&As[k][ty * 8 + 4]);
            float4 b0 = *reinterpret_cast<const float4*>(&Bs[k][tx * 4]);
            float ar[8] = {a0.x, a0.y, a0.z, a0.w, a1.x, a1.y, a1.z, a1.w};
            float br[4] = {b0.x, b0.y, b0.z, b0.w};
            #pragma unroll
            for (int i = 0; i < 8; i++)
                #pragma unroll
                for (int j = 0; j < 4; j++)
                    acc[i][j] = fmaf(ar[i], br[j], acc[i][j]);
        }
        __syncthreads();
    }

    float4 bb = reinterpret_cast<const float4*>(bias)[(n0 >> 2) + tx];
    #pragma unroll
    for (int i = 0; i < 8; i++) {
        int m = m0 + ty * 8 + i;
        float4 o = make_float4(acc[i][0] + bb.x, acc[i][1] + bb.y,
                               acc[i][2] + bb.z, acc[i][3] + bb.w);
        reinterpret_cast<float4*>(g_P)[(size_t)m * (HID / 4) + (n0 >> 2) + tx] = o;
    }
}

// ---------------- persistent RNN: barrier-free tagged dataflow ----------------
// 64 CTAs x 8 warps. Warp w of CTA c owns rows c*16+2w, c*16+2w+1, and stages
// tagged global chunk [w*128, (w+1)*128) into tagged smem. NO __syncthreads in
// the loop: consumers poll tags in smem (volatile, SM-coherent). Global side
// uses relaxed atomics (strong, guaranteed visible). Safety: distance-2
// overwrite induction on the tag protocol (see round log).
__global__ __launch_bounds__(256) void rnn_kernel(const float* __restrict__ Whh,
                                                  float* __restrict__ out) {
    __shared__ unsigned long long sh[2 * HID];   // 16 KB tagged double buffer
    const int warp = threadIdx.x >> 5;
    const int lane = threadIdx.x & 31;
    const int rowA = (blockIdx.x << 4) + (warp << 1);
    const int rowB = rowA + 1;

    for (int i = threadIdx.x; i < 2 * HID; i += 256) sh[i] = 0ull;
    __syncthreads();

    // weights packed as f32x2: row r element pairs (j*64+2L, j*64+2L+1)
    unsigned long long wA[16], wB[16];
    {
        const float2* wra = reinterpret_cast<const float2*>(Whh + (size_t)rowA * HID);
        const float2* wrb = reinterpret_cast<const float2*>(Whh + (size_t)rowB * HID);
        #pragma unroll
        for (int j = 0; j < 16; j++) {
            float2 a = wra[j * 32 + lane];
            float2 b = wrb[j * 32 + lane];
            wA[j] = packff(a.x, a.y);
            wB[j] = packff(b.x, b.y);
        }
    }

    const unsigned shbase = (unsigned)__cvta_generic_to_shared(sh);
    const int gbase = (warp << 7) + (lane << 2);   // 4 global slots per lane
    float pa = g_P[rowA], pb = g_P[rowB];

    for (int t = 0; t < SEQ; ++t) {
        const unsigned tag = (unsigned)(t + 1);    // tag of h_t
        const int par = t & 1;

        float pan = 0.f, pbn = 0.f;
        if (t + 1 < SEQ) {
            pan = g_P[(size_t)(t + 1) * HID + rowA];
            pbn = g_P[(size_t)(t + 1) * HID + rowB];
        }

        // 1) ping-pong 2-deep poll of my 4 global tagged slots
        unsigned long long x0, x1, x2, x3;
        {
            const unsigned long long* gp = g_H + (par << 10) + gbase;
            unsigned long long a0 = ld_rlx(gp), a1 = ld_rlx(gp + 1),
                               a2 = ld_rlx(gp + 2), a3 = ld_rlx(gp + 3);
            for (;;) {
                unsigned long long b0 = ld_rlx(gp), b1 = ld_rlx(gp + 1),
                                   b2 = ld_rlx(gp + 2), b3 = ld_rlx(gp + 3);
                if ((((unsigned)(a0 >> 32) == tag) & ((unsigned)(a1 >> 32) == tag) &
                     ((unsigned)(a2 >> 32) == tag) & ((unsigned)(a3 >> 32) == tag))) {
                    x0 = a0; x1 = a1; x2 = a2; x3 = a3; break;
                }
                a0 = ld_rlx(gp); a1 = ld_rlx(gp + 1);
                a2 = ld_rlx(gp + 2); a3 = ld_rlx(gp + 3);
                if ((((unsigned)(b0 >> 32) == tag) & ((unsigned)(b1 >> 32) == tag) &
                     ((unsigned)(b2 >> 32) == tag) & ((unsigned)(b3 >> 32) == tag))) {
                    x0 = b0; x1 = b1; x2 = b2; x3 = b3; break;
                }
            }
        }

        // 2) stage tagged words to smem (volatile, visible to other warps)
        {
            unsigned sa = shbase + (((par << 10) + gbase) << 3);
            asm volatile("st.volatile.shared.v2.u64 [%0], {%1,%2};" :: "r"(sa), "l"(x0), "l"(x1));
            asm volatile("st.volatile.shared.v2.u64 [%0], {%1,%2};" :: "r"(sa + 16), "l"(x2), "l"(x3));
        }

        // 3) consume all 16 chunks from smem with per-chunk tag spin + f32x2 FMA
        unsigned long long accA0 = 0ull, accA1 = 0ull, accB0 = 0ull, accB1 = 0ull;
        const unsigned hb = shbase + (((par << 10)) << 3) + ((unsigned)lane << 4);
        #pragma unroll
        for (int half = 0; half < 2; half++) {
            unsigned long long p0[8], p1[8];
            #pragma unroll
            for (int j = 0; j < 8; j++) {
                unsigned ad = hb + (unsigned)(((half * 8 + j) << 9));
                asm volatile("ld.volatile.shared.v2.u64 {%0,%1}, [%2];"
                             : "=l"(p0[j]), "=l"(p1[j]) : "r"(ad));
            }
            #pragma unroll
            for (int j = 0; j < 8; j++) {
                unsigned ad = hb + (unsigned)(((half * 8 + j) << 9));
                while (((unsigned)(p0[j] >> 32) != tag) | ((unsigned)(p1[j] >> 32) != tag)) {
                    asm volatile("ld.volatile.shared.v2.u64 {%0,%1}, [%2];"
                                 : "=l"(p0[j]), "=l"(p1[j]) : "r"(ad));
                }
                unsigned long long hp = packlo(p0[j], p1[j]);
                int jj = half * 8 + j;
                if (j & 1) { fma2(accA1, wA[jj], hp); fma2(accB1, wB[jj], hp); }
                else       { fma2(accA0, wA[jj], hp); fma2(accB0, wB[jj], hp); }
            }
        }
        float sa = sum2(accA0, accA1);
        float sb = sum2(accB0, accB1);
        #pragma unroll
        for (int o = 16; o; o >>= 1) {
            sa += __shfl_xor_sync(0xffffffffu, sa, o);
            sb += __shfl_xor_sync(0xffffffffu, sb, o);
        }

        // 4) one tanh (lane-selected); lanes 0/1 publish tagged word FIRST
        float s  = (lane == 0) ? (sa + pa) : (sb + pb);
        float hv = tanhf(s);
        pa = pan; pb = pbn;
        if (lane < 2) {
            int r = rowA + lane;
            unsigned long long wv = ((unsigned long long)(unsigned)(t + 2) << 32)
                                  | (unsigned long long)__float_as_uint(hv);
            st_rlx(g_H + (((t + 1) & 1) << 10) + r, wv);
            out[(size_t)(t + 1) * HID + r] = hv;
        }
    }
}

// ---------------- launch ----------------
extern "C" void kernel_launch(void* const* d_in, const int* in_sizes, int n_in,
                              void* d_out, int out_size) {
    const int*   src  = (const int*)  d_in[0];  // [4096]
    const float* W    = (const float*)d_in[1];  // [32000,1024]
    const float* h0   = (const float*)d_in[2];  // [1024]
    const float* W_hi = (const float*)d_in[3];  // [1024,1024]
    const float* W_hh = (const float*)d_in[4];  // [1024,1024]
    const float* b    = (const float*)d_in[5];  // [1024]
    float* out = (float*)d_out;                 // [4097,1024]

    init_kernel<<<1, 1024>>>(h0, out);
    embed_kernel<<<SEQ, 256>>>(src, W);
    gemm_kernel<<<dim3(HID / BN, SEQ / BM), 256>>>(W_hi, b);
    rnn_kernel<<<NCTA, 256>>>(W_hh, out);
}

// round 5
// speedup vs baseline: 2.2176x; 2.2176x over previous
#include <cuda_runtime.h>

#define SEQ 4096
#define HID 1024
#define NCTA 64
#define EPSF 1e-12f

// Scratch (allocation-free rule: __device__ globals)
__device__ float g_Xn[SEQ * HID];              // normalized embeddings
__device__ float g_P[SEQ * HID];               // W_hi @ x_t + b, precomputed
__device__ unsigned long long g_H[2 * HID];    // tagged h double buffer: hi32=tag, lo32=float bits

// ---------------- strong (relaxed-atomic) 8B ld/st: guaranteed visibility ----------------
__device__ __forceinline__ unsigned long long ld_rlx(const unsigned long long* p) {
    unsigned long long v;
    asm volatile("ld.relaxed.gpu.global.u64 %0, [%1];" : "=l"(v) : "l"(p) : "memory");
    return v;
}
__device__ __forceinline__ void st_rlx(unsigned long long* p, unsigned long long v) {
    asm volatile("st.relaxed.gpu.global.u64 [%0], %1;" :: "l"(p), "l"(v) : "memory");
}

// ---------------- fast tanh: 1 - 2/(e^{2x}+1) via ex2/rcp approx ----------------
__device__ __forceinline__ float fast_tanh(float x) {
    float e;
    asm("ex2.approx.f32 %0, %1;" : "=f"(e) : "f"(x * 2.8853900817779268f)); // 2*log2(e)
    float r;
    asm("rcp.approx.f32 %0, %1;" : "=f"(r) : "f"(e + 1.0f));
    return fmaf(-2.0f, r, 1.0f);
}

// ---------------- init: h0 -> out[0], tagged buf[0] (tag 1), clear buf[1] ----------------
__global__ __launch_bounds__(1024) void init_kernel(const float* __restrict__ h0,
                                                    float* __restrict__ out) {
    int i = threadIdx.x;
    float v = h0[i];
    out[i] = v;
    g_H[i]       = (1ull << 32) | (unsigned long long)__float_as_uint(v);
    g_H[HID + i] = 0ull;
}

// ---------------- embedding + L2 normalize ----------------
__global__ __launch_bounds__(256) void embed_kernel(const int* __restrict__ src,
                                                    const float* __restrict__ W) {
    const int t   = blockIdx.x;
    const int tid = threadIdx.x;
    const float4* row = reinterpret_cast<const float4*>(W) + (size_t)src[t] * (HID / 4);
    float4 v = row[tid];
    float s = v.x * v.x + v.y * v.y + v.z * v.z + v.w * v.w;
    #pragma unroll
    for (int o = 16; o; o >>= 1) s += __shfl_xor_sync(0xffffffffu, s, o);
    __shared__ float red[8];
    if ((tid & 31) == 0) red[tid >> 5] = s;
    __syncthreads();
    float tot = red[0] + red[1] + red[2] + red[3] + red[4] + red[5] + red[6] + red[7];
    float rn = 1.0f / fmaxf(sqrtf(tot), EPSF);
    float4 o4 = make_float4(v.x * rn, v.y * rn, v.z * rn, v.w * rn);
    reinterpret_cast<float4*>(g_Xn)[(size_t)t * (HID / 4) + tid] = o4;
}

// ---------------- GEMM: g_P[m][n] = sum_k g_Xn[m][k] * W_hi[n][k] + b[n] ----------------
#define BM 128
#define BN 64
#define BK 32
__global__ __launch_bounds__(256) void gemm_kernel(const float* __restrict__ Bw,
                                                   const float* __restrict__ bias) {
    __shared__ float As[BK][BM + 4];
    __shared__ float Bs[BK][BN + 4];
    const int tid = threadIdx.x;
    const int m0 = blockIdx.y * BM;
    const int n0 = blockIdx.x * BN;
    const int ty = tid >> 4;
    const int tx = tid & 15;

    float acc[8][4];
    #pragma unroll
    for (int i = 0; i < 8; i++)
        #pragma unroll
        for (int j = 0; j < 4; j++) acc[i][j] = 0.0f;

    for (int k0 = 0; k0 < HID; k0 += BK) {
        #pragma unroll
        for (int i = 0; i < 4; i++) {
            int idx = tid + i * 256;
            int r = idx >> 3;
            int kq = idx & 7;
            float4 f = reinterpret_cast<const float4*>(g_Xn)[(size_t)(m0 + r) * (HID / 4) + (k0 >> 2) + kq];
            As[kq * 4 + 0][r] = f.x;
            As[kq * 4 + 1][r] = f.y;
            As[kq * 4 + 2][r] = f.z;
            As[kq * 4 + 3][r] = f.w;
        }
        #pragma unroll
        for (int i = 0; i < 2; i++) {
            int idx = tid + i * 256;
            int r = idx >> 3;
            int kq = idx & 7;
            float4 f = reinterpret_cast<const float4*>(Bw)[(size_t)(n0 + r) * (HID / 4) + (k0 >> 2) + kq];
            Bs[kq * 4 + 0][r] = f.x;
            Bs[kq * 4 + 1][r] = f.y;
            Bs[kq * 4 + 2][r] = f.z;
            Bs[kq * 4 + 3][r] = f.w;
        }
        __syncthreads();
        #pragma unroll
        for (int k = 0; k < BK; k++) {
            float4 a0 = *reinterpret_cast<const float4*>(&As[k][ty * 8]);
            float4 a1 = *reinterpret_cast<const float4*>(&As[k][ty * 8 + 4]);
            float4 b0 = *reinterpret_cast<const float4*>(&Bs[k][tx * 4]);
            float ar[8] = {a0.x, a0.y, a0.z, a0.w, a1.x, a1.y, a1.z, a1.w};
            float br[4] = {b0.x, b0.y, b0.z, b0.w};
            #pragma unroll
            for (int i = 0; i < 8; i++)
                #pragma unroll
                for (int j = 0; j < 4; j++)
                    acc[i][j] = fmaf(ar[i], br[j], acc[i][j]);
        }
        __syncthreads();
    }

    float4 bb = reinterpret_cast<const float4*>(bias)[(n0 >> 2) + tx];
    #pragma unroll
    for (int i = 0; i < 8; i++) {
        int m = m0 + ty * 8 + i;
        float4 o = make_float4(acc[i][0] + bb.x, acc[i][1] + bb.y,
                               acc[i][2] + bb.z, acc[i][3] + bb.w);
        reinterpret_cast<float4*>(g_P)[(size_t)m * (HID / 4) + (n0 >> 2) + tx] = o;
    }
}

// ---------------- persistent RNN: tagged dataflow + one bar/step ----------------
// 64 CTAs x 8 warps. Warp w of CTA c owns rows c*16+2w, c*16+2w+1, and stages
// global tagged chunk [w*128, (w+1)*128) into plain-float smem. Sync:
// value+step-tag packed in one u64 via relaxed atomics (strong, guaranteed
// visible); 2-deep ping-pong poll halves detect quantization; one
// __syncthreads per step; parity double-buffered smem.
__global__ __launch_bounds__(256) void rnn_kernel(const float* __restrict__ Whh,
                                                  float* __restrict__ out) {
    __shared__ float4 sh[2][HID / 4];            // 8 KB: [parity][h as float4]
    const int warp = threadIdx.x >> 5;
    const int lane = threadIdx.x & 31;
    const int rowA = (blockIdx.x << 4) + (warp << 1);
    const int rowB = rowA + 1;

    // weights for both rows in registers (16 float4 = 64 regs)
    float4 wa[8], wb[8];
    {
        const float4* wra = reinterpret_cast<const float4*>(Whh) + (size_t)rowA * (HID / 4);
        const float4* wrb = wra + (HID / 4);
        #pragma unroll
        for (int j = 0; j < 8; j++) { wa[j] = wra[lane + (j << 5)]; wb[j] = wrb[lane + (j << 5)]; }
    }

    float pa = g_P[rowA], pb = g_P[rowB];
    const int gbase = (warp << 7) + (lane << 2);   // 4 global slots per lane

    for (int t = 0; t < SEQ; ++t) {
        const unsigned tag = (unsigned)(t + 1);    // tag of h_t
        const int par = t & 1;

        // prefetch next-step P (independent of h)
        float pan = 0.f, pbn = 0.f;
        if (t + 1 < SEQ) {
            pan = g_P[(size_t)(t + 1) * HID + rowA];
            pbn = g_P[(size_t)(t + 1) * HID + rowB];
        }

        // 1) 2-deep ping-pong poll of my 4 global tagged slots (relaxed atomics)
        unsigned long long x0, x1, x2, x3;
        {
            const unsigned long long* gp = g_H + (par << 10) + gbase;
            unsigned long long a0 = ld_rlx(gp), a1 = ld_rlx(gp + 1),
                               a2 = ld_rlx(gp + 2), a3 = ld_rlx(gp + 3);
            for (;;) {
                unsigned long long b0 = ld_rlx(gp), b1 = ld_rlx(gp + 1),
                                   b2 = ld_rlx(gp + 2), b3 = ld_rlx(gp + 3);
                if ((((unsigned)(a0 >> 32) == tag) & ((unsigned)(a1 >> 32) == tag) &
                     ((unsigned)(a2 >> 32) == tag) & ((unsigned)(a3 >> 32) == tag))) {
                    x0 = a0; x1 = a1; x2 = a2; x3 = a3; break;
                }
                a0 = ld_rlx(gp); a1 = ld_rlx(gp + 1);
                a2 = ld_rlx(gp + 2); a3 = ld_rlx(gp + 3);
                if ((((unsigned)(b0 >> 32) == tag) & ((unsigned)(b1 >> 32) == tag) &
                     ((unsigned)(b2 >> 32) == tag) & ((unsigned)(b3 >> 32) == tag))) {
                    x0 = b0; x1 = b1; x2 = b2; x3 = b3; break;
                }
            }
        }

        // 2) stage plain floats to smem, then one CTA barrier
        sh[par][gbase >> 2] = make_float4(__uint_as_float((unsigned)x0),
                                          __uint_as_float((unsigned)x1),
                                          __uint_as_float((unsigned)x2),
                                          __uint_as_float((unsigned)x3));
        __syncthreads();

        // 3) dual-row dot product from smem (8 conflict-free LDS.128)
        float a0 = 0.f, a1 = 0.f, b0 = 0.f, b1 = 0.f;
        #pragma unroll
        for (int j = 0; j < 8; j++) {
            float4 h = sh[par][lane + (j << 5)];
            a0 = fmaf(wa[j].x, h.x, a0); a1 = fmaf(wa[j].y, h.y, a1);
            a0 = fmaf(wa[j].z, h.z, a0); a1 = fmaf(wa[j].w, h.w, a1);
            b0 = fmaf(wb[j].x, h.x, b0); b1 = fmaf(wb[j].y, h.y, b1);
            b0 = fmaf(wb[j].z, h.z, b0); b1 = fmaf(wb[j].w, h.w, b1);
        }
        float sa = a0 + a1, sb = b0 + b1;
        #pragma unroll
        for (int o = 16; o; o >>= 1) {
            sa += __shfl_xor_sync(0xffffffffu, sa, o);
            sb += __shfl_xor_sync(0xffffffffu, sb, o);
        }

        // 4) one fast tanh (lane-selected); lanes 0/1 publish tagged word FIRST
        float s  = (lane == 0) ? (sa + pa) : (sb + pb);
        float hv = fast_tanh(s);
        pa = pan; pb = pbn;
        if (lane < 2) {
            int r = rowA + lane;
            unsigned long long wv = ((unsigned long long)(unsigned)(t + 2) << 32)
                                  | (unsigned long long)__float_as_uint(hv);
            st_rlx(g_H + (((t + 1) & 1) << 10) + r, wv);
            out[(size_t)(t + 1) * HID + r] = hv;
        }
    }
}

// ---------------- launch ----------------
extern "C" void kernel_launch(void* const* d_in, const int* in_sizes, int n_in,
                              void* d_out, int out_size) {
    const int*   src  = (const int*)  d_in[0];  // [4096]
    const float* W    = (const float*)d_in[1];  // [32000,1024]
    const float* h0   = (const float*)d_in[2];  // [1024]
    const float* W_hi = (const float*)d_in[3];  // [1024,1024]
    const float* W_hh = (const float*)d_in[4];  // [1024,1024]
    const float* b    = (const float*)d_in[5];  // [1024]
    float* out = (float*)d_out;                 // [4097,1024]

    init_kernel<<<1, 1024>>>(h0, out);
    embed_kernel<<<SEQ, 256>>>(src, W);
    gemm_kernel<<<dim3(HID / BN, SEQ / BM), 256>>>(W_hi, b);
    rnn_kernel<<<NCTA, 256>>>(W_hh, out);
}

// round 6
// speedup vs baseline: 5.3016x; 2.3908x over previous
#include <cuda_runtime.h>

#define SEQ 4096
#define HID 1024
#define NCTA 64
#define EPSF 1e-12f

// Scratch (allocation-free rule: __device__ globals)
__device__ float g_Xn[SEQ * HID];              // normalized embeddings
__device__ float g_P[SEQ * HID];               // W_hi @ x_t + b, precomputed
__device__ unsigned long long g_H[2 * HID];    // tagged h double buffer: hi32=tag, lo32=float bits

// ---------------- weak L2-cached 8B ld/st (fast path) ----------------
__device__ __forceinline__ unsigned long long ld_cg(const unsigned long long* p) {
    unsigned long long v;
    asm volatile("ld.global.cg.u64 %0, [%1];" : "=l"(v) : "l"(p) : "memory");
    return v;
}
__device__ __forceinline__ void st_cg(unsigned long long* p, unsigned long long v) {
    asm volatile("st.global.cg.u64 [%0], %1;" :: "l"(p), "l"(v) : "memory");
}
// ---------------- strong relaxed load (progress-guarantee fallback) ----------------
__device__ __forceinline__ unsigned long long ld_rlx(const unsigned long long* p) {
    unsigned long long v;
    asm volatile("ld.relaxed.gpu.global.u64 %0, [%1];" : "=l"(v) : "l"(p) : "memory");
    return v;
}

// ---------------- fast tanh: 1 - 2/(e^{2x}+1) via ex2/rcp approx ----------------
__device__ __forceinline__ float fast_tanh(float x) {
    float e;
    asm("ex2.approx.f32 %0, %1;" : "=f"(e) : "f"(x * 2.8853900817779268f)); // 2*log2(e)
    float r;
    asm("rcp.approx.f32 %0, %1;" : "=f"(r) : "f"(e + 1.0f));
    return fmaf(-2.0f, r, 1.0f);
}

// ---------------- init: h0 -> out[0], tagged buf[0] (tag 1), clear buf[1] ----------------
__global__ __launch_bounds__(1024) void init_kernel(const float* __restrict__ h0,
                                                    float* __restrict__ out) {
    int i = threadIdx.x;
    float v = h0[i];
    out[i] = v;
    g_H[i]       = (1ull << 32) | (unsigned long long)__float_as_uint(v);
    g_H[HID + i] = 0ull;
}

// ---------------- embedding + L2 normalize ----------------
__global__ __launch_bounds__(256) void embed_kernel(const int* __restrict__ src,
                                                    const float* __restrict__ W) {
    const int t   = blockIdx.x;
    const int tid = threadIdx.x;
    const float4* row = reinterpret_cast<const float4*>(W) + (size_t)src[t] * (HID / 4);
    float4 v = row[tid];
    float s = v.x * v.x + v.y * v.y + v.z * v.z + v.w * v.w;
    #pragma unroll
    for (int o = 16; o; o >>= 1) s += __shfl_xor_sync(0xffffffffu, s, o);
    __shared__ float red[8];
    if ((tid & 31) == 0) red[tid >> 5] = s;
    __syncthreads();
    float tot = red[0] + red[1] + red[2] + red[3] + red[4] + red[5] + red[6] + red[7];
    float rn = 1.0f / fmaxf(sqrtf(tot), EPSF);
    float4 o4 = make_float4(v.x * rn, v.y * rn, v.z * rn, v.w * rn);
    reinterpret_cast<float4*>(g_Xn)[(size_t)t * (HID / 4) + tid] = o4;
}

// ---------------- GEMM: g_P[m][n] = sum_k g_Xn[m][k] * W_hi[n][k] + b[n] ----------------
#define BM 128
#define BN 64
#define BK 32
__global__ __launch_bounds__(256) void gemm_kernel(const float* __restrict__ Bw,
                                                   const float* __restrict__ bias) {
    __shared__ float As[BK][BM + 4];
    __shared__ float Bs[BK][BN + 4];
    const int tid = threadIdx.x;
    const int m0 = blockIdx.y * BM;
    const int n0 = blockIdx.x * BN;
    const int ty = tid >> 4;
    const int tx = tid & 15;

    float acc[8][4];
    #pragma unroll
    for (int i = 0; i < 8; i++)
        #pragma unroll
        for (int j = 0; j < 4; j++) acc[i][j] = 0.0f;

    for (int k0 = 0; k0 < HID; k0 += BK) {
        #pragma unroll
        for (int i = 0; i < 4; i++) {
            int idx = tid + i * 256;
            int r = idx >> 3;
            int kq = idx & 7;
            float4 f = reinterpret_cast<const float4*>(g_Xn)[(size_t)(m0 + r) * (HID / 4) + (k0 >> 2) + kq];
            As[kq * 4 + 0][r] = f.x;
            As[kq * 4 + 1][r] = f.y;
            As[kq * 4 + 2][r] = f.z;
            As[kq * 4 + 3][r] = f.w;
        }
        #pragma unroll
        for (int i = 0; i < 2; i++) {
            int idx = tid + i * 256;
            int r = idx >> 3;
            int kq = idx & 7;
            float4 f = reinterpret_cast<const float4*>(Bw)[(size_t)(n0 + r) * (HID / 4) + (k0 >> 2) + kq];
            Bs[kq * 4 + 0][r] = f.x;
            Bs[kq * 4 + 1][r] = f.y;
            Bs[kq * 4 + 2][r] = f.z;
            Bs[kq * 4 + 3][r] = f.w;
        }
        __syncthreads();
        #pragma unroll
        for (int k = 0; k < BK; k++) {
            float4 a0 = *reinterpret_cast<const float4*>(&As[k][ty * 8]);
            float4 a1 = *reinterpret_cast<const float4*>(&As[k][ty * 8 + 4]);
            float4 b0 = *reinterpret_cast<const float4*>(&Bs[k][tx * 4]);
            float ar[8] = {a0.x, a0.y, a0.z, a0.w, a1.x, a1.y, a1.z, a1.w};
            float br[4] = {b0.x, b0.y, b0.z, b0.w};
            #pragma unroll
            for (int i = 0; i < 8; i++)
                #pragma unroll
                for (int j = 0; j < 4; j++)
                    acc[i][j] = fmaf(ar[i], br[j], acc[i][j]);
        }
        __syncthreads();
    }

    float4 bb = reinterpret_cast<const float4*>(bias)[(n0 >> 2) + tx];
    #pragma unroll
    for (int i = 0; i < 8; i++) {
        int m = m0 + ty * 8 + i;
        float4 o = make_float4(acc[i][0] + bb.x, acc[i][1] + bb.y,
                               acc[i][2] + bb.z, acc[i][3] + bb.w);
        reinterpret_cast<float4*>(g_P)[(size_t)m * (HID / 4) + (n0 >> 2) + tx] = o;
    }
}

// ---------------- persistent RNN: tagged dataflow + one bar/step ----------------
// 64 CTAs x 8 warps. Warp w of CTA c owns rows c*16+2w, c*16+2w+1, and stages
// global tagged chunk [w*128, (w+1)*128) into plain-float smem.
// Sync: value+step-tag packed in one u64. Fast path: weak .cg (L2-cached,
// ~240cyc RT). Every 32 failed spins: strong relaxed load (formal progress
// guarantee -> cannot hang). One __syncthreads per step; parity-double smem.
__global__ __launch_bounds__(256) void rnn_kernel(const float* __restrict__ Whh,
                                                  float* __restrict__ out) {
    __shared__ float4 sh[2][HID / 4];            // 8 KB: [parity][h as float4]
    const int warp = threadIdx.x >> 5;
    const int lane = threadIdx.x & 31;
    const int rowA = (blockIdx.x << 4) + (warp << 1);
    const int rowB = rowA + 1;

    // weights for both rows in registers (16 float4 = 64 regs)
    float4 wa[8], wb[8];
    {
        const float4* wra = reinterpret_cast<const float4*>(Whh) + (size_t)rowA * (HID / 4);
        const float4* wrb = wra + (HID / 4);
        #pragma unroll
        for (int j = 0; j < 8; j++) { wa[j] = wra[lane + (j << 5)]; wb[j] = wrb[lane + (j << 5)]; }
    }

    float pa = g_P[rowA], pb = g_P[rowB];
    const int gbase = (warp << 7) + (lane << 2);   // 4 global slots per lane

    for (int t = 0; t < SEQ; ++t) {
        const unsigned tag = (unsigned)(t + 1);    // tag of h_t
        const int par = t & 1;

        // prefetch next-step P (independent of h)
        float pan = 0.f, pbn = 0.f;
        if (t + 1 < SEQ) {
            pan = g_P[(size_t)(t + 1) * HID + rowA];
            pbn = g_P[(size_t)(t + 1) * HID + rowB];
        }

        // 1) poll my 4 global tagged slots: weak .cg fast path + strong fallback
        unsigned long long v0, v1, v2, v3;
        {
            const unsigned long long* gp = g_H + (par << 10) + gbase;
            int spins = 0;
            for (;;) {
                v0 = ld_cg(gp);     v1 = ld_cg(gp + 1);
                v2 = ld_cg(gp + 2); v3 = ld_cg(gp + 3);
                if ((((unsigned)(v0 >> 32) == tag) & ((unsigned)(v1 >> 32) == tag) &
                     ((unsigned)(v2 >> 32) == tag) & ((unsigned)(v3 >> 32) == tag))) break;
                if ((++spins & 31) == 0) {
                    v0 = ld_rlx(gp);     v1 = ld_rlx(gp + 1);
                    v2 = ld_rlx(gp + 2); v3 = ld_rlx(gp + 3);
                    if ((((unsigned)(v0 >> 32) == tag) & ((unsigned)(v1 >> 32) == tag) &
                         ((unsigned)(v2 >> 32) == tag) & ((unsigned)(v3 >> 32) == tag))) break;
                }
            }
        }

        // 2) stage plain floats to smem, then one CTA barrier
        sh[par][gbase >> 2] = make_float4(__uint_as_float((unsigned)v0),
                                          __uint_as_float((unsigned)v1),
                                          __uint_as_float((unsigned)v2),
                                          __uint_as_float((unsigned)v3));
        __syncthreads();

        // 3) dual-row dot product from smem (8 conflict-free LDS.128)
        float a0 = 0.f, a1 = 0.f, b0 = 0.f, b1 = 0.f;
        #pragma unroll
        for (int j = 0; j < 8; j++) {
            float4 h = sh[par][lane + (j << 5)];
            a0 = fmaf(wa[j].x, h.x, a0); a1 = fmaf(wa[j].y, h.y, a1);
            a0 = fmaf(wa[j].z, h.z, a0); a1 = fmaf(wa[j].w, h.w, a1);
            b0 = fmaf(wb[j].x, h.x, b0); b1 = fmaf(wb[j].y, h.y, b1);
            b0 = fmaf(wb[j].z, h.z, b0); b1 = fmaf(wb[j].w, h.w, b1);
        }
        float sa = a0 + a1, sb = b0 + b1;
        #pragma unroll
        for (int o = 16; o; o >>= 1) {
            sa += __shfl_xor_sync(0xffffffffu, sa, o);
            sb += __shfl_xor_sync(0xffffffffu, sb, o);
        }

        // 4) one fast tanh (lane-selected); lanes 0/1 publish tagged word FIRST
        float s  = (lane == 0) ? (sa + pa) : (sb + pb);
        float hv = fast_tanh(s);
        pa = pan; pb = pbn;
        if (lane < 2) {
            int r = rowA + lane;
            unsigned long long wv = ((unsigned long long)(unsigned)(t + 2) << 32)
                                  | (unsigned long long)__float_as_uint(hv);
            st_cg(g_H + (((t + 1) & 1) << 10) + r, wv);
            out[(size_t)(t + 1) * HID + r] = hv;
        }
    }
}

// ---------------- launch ----------------
extern "C" void kernel_launch(void* const* d_in, const int* in_sizes, int n_in,
                              void* d_out, int out_size) {
    const int*   src  = (const int*)  d_in[0];  // [4096]
    const float* W    = (const float*)d_in[1];  // [32000,1024]
    const float* h0   = (const float*)d_in[2];  // [1024]
    const float* W_hi = (const float*)d_in[3];  // [1024,1024]
    const float* W_hh = (const float*)d_in[4];  // [1024,1024]
    const float* b    = (const float*)d_in[5];  // [1024]
    float* out = (float*)d_out;                 // [4097,1024]

    init_kernel<<<1, 1024>>>(h0, out);
    embed_kernel<<<SEQ, 256>>>(src, W);
    gemm_kernel<<<dim3(HID / BN, SEQ / BM), 256>>>(W_hi, b);
    rnn_kernel<<<NCTA, 256>>>(W_hh, out);
}

// round 7
// speedup vs baseline: 5.5495x; 1.0468x over previous
#include <cuda_runtime.h>

#define SEQ 4096
#define HID 1024
#define NCTA 32
#define EPSF 1e-12f

// Scratch (allocation-free rule: __device__ globals)
__device__ float g_Xn[SEQ * HID];              // normalized embeddings
__device__ float g_P[SEQ * HID];               // W_hi @ x_t + b, precomputed
__device__ unsigned long long g_H[2 * HID];    // tagged h double buffer: hi32=tag, lo32=float bits

// ---------------- weak L2-cached ld/st (fast path) ----------------
__device__ __forceinline__ void ld_cg_v2(const unsigned long long* p,
                                         unsigned long long& a, unsigned long long& b) {
    asm volatile("ld.global.cg.v2.u64 {%0,%1}, [%2];" : "=l"(a), "=l"(b) : "l"(p) : "memory");
}
__device__ __forceinline__ void st_cg_v2(unsigned long long* p,
                                         unsigned long long a, unsigned long long b) {
    asm volatile("st.global.cg.v2.u64 [%0], {%1,%2};" :: "l"(p), "l"(a), "l"(b) : "memory");
}
// ---------------- strong relaxed load (progress-guarantee fallback) ----------------
__device__ __forceinline__ unsigned long long ld_rlx(const unsigned long long* p) {
    unsigned long long v;
    asm volatile("ld.relaxed.gpu.global.u64 %0, [%1];" : "=l"(v) : "l"(p) : "memory");
    return v;
}

// ---------------- fast tanh: 1 - 2/(e^{2x}+1) via ex2/rcp approx ----------------
__device__ __forceinline__ float fast_tanh(float x) {
    float e;
    asm("ex2.approx.f32 %0, %1;" : "=f"(e) : "f"(x * 2.8853900817779268f)); // 2*log2(e)
    float r;
    asm("rcp.approx.f32 %0, %1;" : "=f"(r) : "f"(e + 1.0f));
    return fmaf(-2.0f, r, 1.0f);
}

// ---------------- init: h0 -> out[0], tagged buf[0] (tag 1), clear buf[1] ----------------
__global__ __launch_bounds__(1024) void init_kernel(const float* __restrict__ h0,
                                                    float* __restrict__ out) {
    int i = threadIdx.x;
    float v = h0[i];
    out[i] = v;
    g_H[i]       = (1ull << 32) | (unsigned long long)__float_as_uint(v);
    g_H[HID + i] = 0ull;
}

// ---------------- embedding + L2 normalize ----------------
__global__ __launch_bounds__(256) void embed_kernel(const int* __restrict__ src,
                                                    const float* __restrict__ W) {
    const int t   = blockIdx.x;
    const int tid = threadIdx.x;
    const float4* row = reinterpret_cast<const float4*>(W) + (size_t)src[t] * (HID / 4);
    float4 v = row[tid];
    float s = v.x * v.x + v.y * v.y + v.z * v.z + v.w * v.w;
    #pragma unroll
    for (int o = 16; o; o >>= 1) s += __shfl_xor_sync(0xffffffffu, s, o);
    __shared__ float red[8];
    if ((tid & 31) == 0) red[tid >> 5] = s;
    __syncthreads();
    float tot = red[0] + red[1] + red[2] + red[3] + red[4] + red[5] + red[6] + red[7];
    float rn = 1.0f / fmaxf(sqrtf(tot), EPSF);
    float4 o4 = make_float4(v.x * rn, v.y * rn, v.z * rn, v.w * rn);
    reinterpret_cast<float4*>(g_Xn)[(size_t)t * (HID / 4) + tid] = o4;
}

// ---------------- GEMM: g_P[m][n] = sum_k g_Xn[m][k] * W_hi[n][k] + b[n] ----------------
#define BM 128
#define BN 64
#define BK 32
__global__ __launch_bounds__(256) void gemm_kernel(const float* __restrict__ Bw,
                                                   const float* __restrict__ bias) {
    __shared__ float As[BK][BM + 4];
    __shared__ float Bs[BK][BN + 4];
    const int tid = threadIdx.x;
    const int m0 = blockIdx.y * BM;
    const int n0 = blockIdx.x * BN;
    const int ty = tid >> 4;
    const int tx = tid & 15;

    float acc[8][4];
    #pragma unroll
    for (int i = 0; i < 8; i++)
        #pragma unroll
        for (int j = 0; j < 4; j++) acc[i][j] = 0.0f;

    for (int k0 = 0; k0 < HID; k0 += BK) {
        #pragma unroll
        for (int i = 0; i < 4; i++) {
            int idx = tid + i * 256;
            int r = idx >> 3;
            int kq = idx & 7;
            float4 f = reinterpret_cast<const float4*>(g_Xn)[(size_t)(m0 + r) * (HID / 4) + (k0 >> 2) + kq];
            As[kq * 4 + 0][r] = f.x;
            As[kq * 4 + 1][r] = f.y;
            As[kq * 4 + 2][r] = f.z;
            As[kq * 4 + 3][r] = f.w;
        }
        #pragma unroll
        for (int i = 0; i < 2; i++) {
            int idx = tid + i * 256;
            int r = idx >> 3;
            int kq = idx & 7;
            float4 f = reinterpret_cast<const float4*>(Bw)[(size_t)(n0 + r) * (HID / 4) + (k0 >> 2) + kq];
            Bs[kq * 4 + 0][r] = f.x;
            Bs[kq * 4 + 1][r] = f.y;
            Bs[kq * 4 + 2][r] = f.z;
            Bs[kq * 4 + 3][r] = f.w;
        }
        __syncthreads();
        #pragma unroll
        for (int k = 0; k < BK; k++) {
            float4 a0 = *reinterpret_cast<const float4*>(&As[k][ty * 8]);
            float4 a1 = *reinterpret_cast<const float4*>(&As[k][ty * 8 + 4]);
            float4 b0 = *reinterpret_cast<const float4*>(&Bs[k][tx * 4]);
            float ar[8] = {a0.x, a0.y, a0.z, a0.w, a1.x, a1.y, a1.z, a1.w};
            float br[4] = {b0.x, b0.y, b0.z, b0.w};
            #pragma unroll
            for (int i = 0; i < 8; i++)
                #pragma unroll
                for (int j = 0; j < 4; j++)
                    acc[i][j] = fmaf(ar[i], br[j], acc[i][j]);
        }
        __syncthreads();
    }

    float4 bb = reinterpret_cast<const float4*>(bias)[(n0 >> 2) + tx];
    #pragma unroll
    for (int i = 0; i < 8; i++) {
        int m = m0 + ty * 8 + i;
        float4 o = make_float4(acc[i][0] + bb.x, acc[i][1] + bb.y,
                               acc[i][2] + bb.z, acc[i][3] + bb.w);
        reinterpret_cast<float4*>(g_P)[(size_t)m * (HID / 4) + (n0 >> 2) + tx] = o;
    }
}

// ---------------- persistent RNN: tagged dataflow, 32 CTAs, paced poll ----------------
// 32 CTAs x 16 warps (512 thr). Warp w of CTA c owns rows c*32+2w, c*32+2w+1,
// and stages global tagged chunk [w*64, (w+1)*64) into plain-float smem
// (one 16B v2.u64 poll load per lane). Sync: value+step-tag in one u64 via
// weak .cg (L2-cached) + nanosleep pacing (kills the polling storm) + strong
// relaxed fallback every 16 spins (formal progress guarantee). One
// __syncthreads per step; parity double-buffered smem; distance-2 overwrite
// induction unchanged.
__global__ __launch_bounds__(512) void rnn_kernel(const float* __restrict__ Whh,
                                                  float* __restrict__ out) {
    __shared__ float shf[2][HID];                // 8 KB: [parity][h]
    const int warp = threadIdx.x >> 5;
    const int lane = threadIdx.x & 31;
    const int rowA = (blockIdx.x << 5) + (warp << 1);
    const int rowB = rowA + 1;

    // weights for both rows in registers (16 float4 = 64 regs)
    float4 wa[8], wb[8];
    {
        const float4* wra = reinterpret_cast<const float4*>(Whh) + (size_t)rowA * (HID / 4);
        const float4* wrb = wra + (HID / 4);
        #pragma unroll
        for (int j = 0; j < 8; j++) { wa[j] = wra[lane + (j << 5)]; wb[j] = wrb[lane + (j << 5)]; }
    }

    float pa = g_P[rowA], pb = g_P[rowB];
    const int slot = (warp << 6) + (lane << 1);    // 2 u64 slots per lane

    for (int t = 0; t < SEQ; ++t) {
        const unsigned tag = (unsigned)(t + 1);    // tag of h_t
        const int par = t & 1;

        // prefetch next-step P (independent of h)
        float pan = 0.f, pbn = 0.f;
        if (t + 1 < SEQ) {
            pan = g_P[(size_t)(t + 1) * HID + rowA];
            pbn = g_P[(size_t)(t + 1) * HID + rowB];
        }

        // 1) poll my 2 tagged slots: one 16B .cg load; nanosleep pacing on miss
        unsigned long long v0, v1;
        {
            const unsigned long long* gp = g_H + (par << 10) + slot;
            int spins = 0;
            for (;;) {
                ld_cg_v2(gp, v0, v1);
                if ((((unsigned)(v0 >> 32) == tag) & ((unsigned)(v1 >> 32) == tag))) break;
                if ((++spins & 15) == 0) {
                    v0 = ld_rlx(gp); v1 = ld_rlx(gp + 1);
                    if ((((unsigned)(v0 >> 32) == tag) & ((unsigned)(v1 >> 32) == tag))) break;
                }
                asm volatile("nanosleep.u32 128;");
            }
        }

        // 2) stage plain floats to smem, then one CTA barrier
        reinterpret_cast<float2*>(shf[par])[slot >> 1] =
            make_float2(__uint_as_float((unsigned)v0), __uint_as_float((unsigned)v1));
        __syncthreads();

        // 3) dual-row dot product from smem (8 conflict-free LDS.128 per row-pair)
        const float4* hv4 = reinterpret_cast<const float4*>(shf[par]);
        float a0 = 0.f, a1 = 0.f, b0 = 0.f, b1 = 0.f;
        #pragma unroll
        for (int j = 0; j < 8; j++) {
            float4 h = hv4[lane + (j << 5)];
            a0 = fmaf(wa[j].x, h.x, a0); a1 = fmaf(wa[j].y, h.y, a1);
            a0 = fmaf(wa[j].z, h.z, a0); a1 = fmaf(wa[j].w, h.w, a1);
            b0 = fmaf(wb[j].x, h.x, b0); b1 = fmaf(wb[j].y, h.y, b1);
            b0 = fmaf(wb[j].z, h.z, b0); b1 = fmaf(wb[j].w, h.w, b1);
        }
        float sa = a0 + a1, sb = b0 + b1;
        #pragma unroll
        for (int o = 16; o; o >>= 1) {
            sa += __shfl_xor_sync(0xffffffffu, sa, o);
            sb += __shfl_xor_sync(0xffffffffu, sb, o);
        }

        // 4) lane 0: both tanhs, one 16B tagged publish + one 8B out store
        if (lane == 0) {
            float hA = fast_tanh(sa + pa);
            float hB = fast_tanh(sb + pb);
            unsigned long long tg = (unsigned long long)(unsigned)(t + 2) << 32;
            st_cg_v2(g_H + (((t + 1) & 1) << 10) + rowA,
                     tg | (unsigned long long)__float_as_uint(hA),
                     tg | (unsigned long long)__float_as_uint(hB));
            reinterpret_cast<float2*>(out + (size_t)(t + 1) * HID)[rowA >> 1] =
                make_float2(hA, hB);
        }
        pa = pan; pb = pbn;
    }
}

// ---------------- launch ----------------
extern "C" void kernel_launch(void* const* d_in, const int* in_sizes, int n_in,
                              void* d_out, int out_size) {
    const int*   src  = (const int*)  d_in[0];  // [4096]
    const float* W    = (const float*)d_in[1];  // [32000,1024]
    const float* h0   = (const float*)d_in[2];  // [1024]
    const float* W_hi = (const float*)d_in[3];  // [1024,1024]
    const float* W_hh = (const float*)d_in[4];  // [1024,1024]
    const float* b    = (const float*)d_in[5];  // [1024]
    float* out = (float*)d_out;                 // [4097,1024]

    init_kernel<<<1, 1024>>>(h0, out);
    embed_kernel<<<SEQ, 256>>>(src, W);
    gemm_kernel<<<dim3(HID / BN, SEQ / BM), 256>>>(W_hi, b);
    rnn_kernel<<<NCTA, 512>>>(W_hh, out);
}